// round 2
// baseline (speedup 1.0000x reference)
#include <cuda_runtime.h>
#include <cuda_bf16.h>

// GGIN: 3-layer GIN + graph readout.
// Shapes (from reference): N=100000 nodes, E=1600000 edges, D=128, G=1024 graphs,
// L=3 layers, C=128 classes, NI=100000 init nodes, NL=64 lead rows.
//
// Restructuring:
//   ctxg[g]  = segsum(init_feat)[g] + sum(lead_feat)          (per-graph, [G,D])
//   pg_l[g]  = hg[g]@W[l] + ctxg[g]@Wc[l] + b[l]              (per-graph, [G,D])
//   h'       = relu( ((1+eps)h + agg) @ W[l] + pg_l[gid] )    (node-level GEMM)
//   hg'      = segsum(h')  (fused into GEMM epilogue via vector reds)
//   agg      = segsum(h[src] at dst)  (edge scatter, vector reds)
// Final: out = relu(hg@fc1+b1)@fc2+b2.

#define D 128
#define MAXN 100000
#define MAXG 1024

// ---- static scratch (no cudaMalloc allowed) ----
__device__ float g_h0[(size_t)MAXN * D];
__device__ float g_h1[(size_t)MAXN * D];
__device__ float g_agg[(size_t)MAXN * D];
__device__ float g_hgA[MAXG * D];
__device__ float g_hgB[MAXG * D];
__device__ float g_ctx[MAXG * D];
__device__ float g_pg[MAXG * D];
__device__ float g_t[MAXG * D];
__device__ float g_lead[D];

// ---- helpers ----
__device__ __forceinline__ void red4(float* p, float4 v) {
    asm volatile("red.global.add.v4.f32 [%0], {%1,%2,%3,%4};"
                 :: "l"(p), "f"(v.x), "f"(v.y), "f"(v.z), "f"(v.w) : "memory");
}
__device__ __forceinline__ unsigned long long pack2(float x, float y) {
    unsigned long long r;
    asm("mov.b64 %0, {%1,%2};" : "=l"(r) : "f"(x), "f"(y));
    return r;
}
__device__ __forceinline__ void fma2(unsigned long long& d, unsigned long long a, unsigned long long b) {
    asm("fma.rn.f32x2 %0, %1, %2, %0;" : "+l"(d) : "l"(a), "l"(b));
}
__device__ __forceinline__ float2 unpack2(unsigned long long v) {
    float2 r;
    asm("mov.b64 {%0,%1}, %2;" : "=f"(r.x), "=f"(r.y) : "l"(v));
    return r;
}

// ---- zero ----
__global__ void k_zero(float4* __restrict__ p, int n4) {
    int stride = gridDim.x * blockDim.x;
    for (int i = blockIdx.x * blockDim.x + threadIdx.x; i < n4; i += stride)
        p[i] = make_float4(0.f, 0.f, 0.f, 0.f);
}

// ---- lead sum: one block, 128 threads ----
__global__ void k_lead(const float* __restrict__ lf, float* __restrict__ lead, int nl) {
    int d = threadIdx.x;
    float a = 0.f;
    for (int r = 0; r < nl; r++) a += lf[r * D + d];
    lead[d] = a;
}

// ---- ctx += lead ----
__global__ void k_addlead(float* __restrict__ ctx, const float* __restrict__ lead, int n) {
    int i = blockIdx.x * blockDim.x + threadIdx.x;
    if (i < n) ctx[i] += lead[i & (D - 1)];
}

// ---- row segment-sum scatter: warp per row, lane per float4 ----
__global__ void k_scatter_rows(const float4* __restrict__ rows, const int* __restrict__ ids,
                               float* __restrict__ out, int n) {
    int t = blockIdx.x * blockDim.x + threadIdx.x;
    int r = t >> 5, lane = t & 31;
    if (r >= n) return;
    int g = __ldg(ids + r);
    float4 v = __ldg(rows + (size_t)r * 32 + lane);
    red4(out + (size_t)g * D + lane * 4, v);
}

// ---- edge scatter: agg[dst] += h[src]; warp per edge ----
__global__ void k_edge(const float4* __restrict__ h, const int* __restrict__ src,
                       const int* __restrict__ dst, float* __restrict__ agg, int nE) {
    int t = blockIdx.x * blockDim.x + threadIdx.x;
    int e = t >> 5, lane = t & 31;
    if (e >= nE) return;
    int s = __ldg(src + e);
    int d = __ldg(dst + e);
    float4 v = __ldg(h + (size_t)s * 32 + lane);
    red4(agg + (size_t)d * D + lane * 4, v);
}

// ---- per-graph bias: pg[g] = hg[g]@W + ctx[g]@Wc + b ----
__global__ void k_pg(const float* __restrict__ hg, const float* __restrict__ ctx,
                     const float* __restrict__ W, const float* __restrict__ Wc,
                     const float* __restrict__ b, float* __restrict__ pg) {
    int g = blockIdx.x, d = threadIdx.x;
    __shared__ float sh[D], sc[D];
    sh[d] = hg[g * D + d];
    sc[d] = ctx[g * D + d];
    __syncthreads();
    float acc = __ldg(b + d);
    #pragma unroll 8
    for (int k = 0; k < D; k++) {
        acc += sh[k] * __ldg(W + k * D + d);
        acc += sc[k] * __ldg(Wc + k * D + d);
    }
    pg[g * D + d] = acc;
}

// ---- small dense: out[g] = (relu?)(in[g]@Wm + bias) ----
__global__ void k_fc(const float* __restrict__ in, const float* __restrict__ Wm,
                     const float* __restrict__ bias, float* __restrict__ out, int do_relu) {
    int g = blockIdx.x, d = threadIdx.x;
    __shared__ float s[D];
    s[d] = in[g * D + d];
    __syncthreads();
    float acc = __ldg(bias + d);
    #pragma unroll 8
    for (int k = 0; k < D; k++) acc += s[k] * __ldg(Wm + k * D + d);
    if (do_relu) acc = fmaxf(acc, 0.f);
    out[g * D + d] = acc;
}

// ---- main node GEMM: Hout = relu(((1+eps)Hin + Agg)@W + pg[gid]); hgOut += segsum; Agg=0 ----
#define SMEM_GEMM ((128 * 132 + 128 * 128) * 4)
__global__ void __launch_bounds__(256, 1)
k_gemm(const float4* __restrict__ Hin4, float* __restrict__ Agg,
       const float4* __restrict__ Wl4, const float* __restrict__ pgv,
       const int* __restrict__ gid, const float* __restrict__ epsArr, int l,
       float4* __restrict__ Hout4, float* __restrict__ hgOut, int nRows) {
    extern __shared__ float smem[];
    float* As = smem;              // [128][132]  (row-major m x k, padded)
    float* Bs = smem + 128 * 132;  // [128][128]  (k x n)
    const int tid = threadIdx.x;
    const int m0 = blockIdx.x * 128;
    const float sc = 1.0f + __ldg(epsArr + l);
    float4* Agg4 = (float4*)Agg;

    float4* Bs4 = (float4*)Bs;
    #pragma unroll
    for (int i = 0; i < 16; i++) {
        int li = tid + i * 256;
        Bs4[li] = __ldg(Wl4 + li);
    }
    #pragma unroll
    for (int i = 0; i < 16; i++) {
        int li = tid + i * 256;
        int m = li >> 5, k4 = li & 31;
        int mg = m0 + m;
        float4 v = make_float4(0.f, 0.f, 0.f, 0.f);
        if (mg < nRows) {
            float4 hv = __ldg(Hin4 + (size_t)mg * 32 + k4);
            float4 av = Agg4[(size_t)mg * 32 + k4];
            v.x = fmaf(sc, hv.x, av.x);
            v.y = fmaf(sc, hv.y, av.y);
            v.z = fmaf(sc, hv.z, av.z);
            v.w = fmaf(sc, hv.w, av.w);
        }
        *(float4*)(As + m * 132 + k4 * 4) = v;
    }
    __syncthreads();

    const int tx = tid & 15, ty = tid >> 4;
    unsigned long long acc[8][4];
    #pragma unroll
    for (int i = 0; i < 8; i++)
        #pragma unroll
        for (int j = 0; j < 4; j++) acc[i][j] = 0ull;

    const float* a0 = As + (ty * 4) * 132;
    const float* a1 = As + (64 + ty * 4) * 132;

    #pragma unroll 8
    for (int k = 0; k < 128; k++) {
        float4 b0 = *(const float4*)(Bs + k * 128 + tx * 4);
        float4 b1 = *(const float4*)(Bs + k * 128 + 64 + tx * 4);
        unsigned long long bb0 = pack2(b0.x, b0.y), bb1 = pack2(b0.z, b0.w);
        unsigned long long bb2 = pack2(b1.x, b1.y), bb3 = pack2(b1.z, b1.w);
        #pragma unroll
        for (int i = 0; i < 4; i++) {
            float a = a0[i * 132 + k];
            unsigned long long aa = pack2(a, a);
            fma2(acc[i][0], aa, bb0);
            fma2(acc[i][1], aa, bb1);
            fma2(acc[i][2], aa, bb2);
            fma2(acc[i][3], aa, bb3);
        }
        #pragma unroll
        for (int i = 0; i < 4; i++) {
            float a = a1[i * 132 + k];
            unsigned long long aa = pack2(a, a);
            fma2(acc[4 + i][0], aa, bb0);
            fma2(acc[4 + i][1], aa, bb1);
            fma2(acc[4 + i][2], aa, bb2);
            fma2(acc[4 + i][3], aa, bb3);
        }
    }

    // zero agg rows for the next layer's scatter (block-private rows)
    #pragma unroll
    for (int i = 0; i < 16; i++) {
        int li = tid + i * 256;
        int m = li >> 5, k4 = li & 31;
        int mg = m0 + m;
        if (mg < nRows) Agg4[(size_t)mg * 32 + k4] = make_float4(0.f, 0.f, 0.f, 0.f);
    }

    // epilogue
    #pragma unroll
    for (int i = 0; i < 8; i++) {
        int m = (i < 4) ? (ty * 4 + i) : (64 + ty * 4 + i - 4);
        int mg = m0 + m;
        if (mg >= nRows) continue;
        int g = __ldg(gid + mg);
        const float4* pgr = (const float4*)(pgv + (size_t)g * D);
        float4 p0 = __ldg(pgr + tx);
        float4 p1 = __ldg(pgr + 16 + tx);
        float2 t0 = unpack2(acc[i][0]), t1 = unpack2(acc[i][1]);
        float2 t2 = unpack2(acc[i][2]), t3 = unpack2(acc[i][3]);
        float4 o0 = make_float4(fmaxf(t0.x + p0.x, 0.f), fmaxf(t0.y + p0.y, 0.f),
                                fmaxf(t1.x + p0.z, 0.f), fmaxf(t1.y + p0.w, 0.f));
        float4 o1 = make_float4(fmaxf(t2.x + p1.x, 0.f), fmaxf(t2.y + p1.y, 0.f),
                                fmaxf(t3.x + p1.z, 0.f), fmaxf(t3.y + p1.w, 0.f));
        Hout4[(size_t)mg * 32 + tx] = o0;
        Hout4[(size_t)mg * 32 + 16 + tx] = o1;
        red4(hgOut + (size_t)g * D + tx * 4, o0);
        red4(hgOut + (size_t)g * D + 64 + tx * 4, o1);
    }
}

extern "C" void kernel_launch(void* const* d_in, const int* in_sizes, int n_in,
                              void* d_out, int out_size) {
    const float* x        = (const float*)d_in[0];
    const int*   src      = (const int*)d_in[1];
    const int*   dst      = (const int*)d_in[2];
    const int*   gids     = (const int*)d_in[3];
    const float* initf    = (const float*)d_in[4];
    const int*   init_ids = (const int*)d_in[5];
    const float* leadf    = (const float*)d_in[6];
    const float* W        = (const float*)d_in[7];
    const float* Wc       = (const float*)d_in[8];
    const float* b        = (const float*)d_in[9];
    const float* eps      = (const float*)d_in[10];
    const float* fc1_w    = (const float*)d_in[11];
    const float* fc1_b    = (const float*)d_in[12];
    const float* fc2_w    = (const float*)d_in[13];
    const float* fc2_b    = (const float*)d_in[14];

    const int N  = in_sizes[0] / D;
    const int E  = in_sizes[1];
    const int NI = in_sizes[4] / D;
    const int NL = in_sizes[6] / D;
    const int L  = in_sizes[10];
    const int G  = out_size / D;  // C == D == 128

    float *h0, *h1, *agg, *hgA, *hgB, *ctx, *pg, *tbuf, *lead;
    cudaGetSymbolAddress((void**)&h0, g_h0);
    cudaGetSymbolAddress((void**)&h1, g_h1);
    cudaGetSymbolAddress((void**)&agg, g_agg);
    cudaGetSymbolAddress((void**)&hgA, g_hgA);
    cudaGetSymbolAddress((void**)&hgB, g_hgB);
    cudaGetSymbolAddress((void**)&ctx, g_ctx);
    cudaGetSymbolAddress((void**)&pg, g_pg);
    cudaGetSymbolAddress((void**)&tbuf, g_t);
    cudaGetSymbolAddress((void**)&lead, g_lead);

    cudaFuncSetAttribute(k_gemm, cudaFuncAttributeMaxDynamicSharedMemorySize, SMEM_GEMM);

    // init: zero accumulators
    k_zero<<<1024, 256>>>((float4*)agg, N * D / 4);
    k_zero<<<32, 256>>>((float4*)hgA, G * D / 4);
    k_zero<<<32, 256>>>((float4*)ctx, G * D / 4);

    // global context
    k_lead<<<1, D>>>(leadf, lead, NL);
    k_scatter_rows<<<(N * 32 + 255) / 256, 256>>>((const float4*)x, gids, hgA, N);
    k_scatter_rows<<<(NI * 32 + 255) / 256, 256>>>((const float4*)initf, init_ids, ctx, NI);
    k_addlead<<<(G * D + 255) / 256, 256>>>(ctx, lead, G * D);

    const float* hin = x;
    float* hbuf[2] = {h0, h1};
    float* hg_in = hgA;
    float* hg_out = hgB;

    for (int l = 0; l < L; l++) {
        float* hout = hbuf[l & 1];
        // edge aggregation into agg (pre-zeroed)
        k_edge<<<(E * 32 + 255) / 256, 256>>>((const float4*)hin, src, dst, agg, E);
        // per-graph bias
        k_pg<<<G, D>>>(hg_in, ctx, W + (size_t)l * D * D, Wc + (size_t)l * D * D, b + l * D, pg);
        // zero next-layer graph sums
        k_zero<<<32, 256>>>((float4*)hg_out, G * D / 4);
        // node GEMM + relu + graph-sum + agg reset
        k_gemm<<<(N + 127) / 128, 256, SMEM_GEMM>>>(
            (const float4*)hin, agg, (const float4*)(W + (size_t)l * D * D),
            pg, gids, eps, l, (float4*)hout, hg_out, N);
        hin = hout;
        float* tmp = hg_in; hg_in = hg_out; hg_out = tmp;
    }

    // readout MLP: out = relu(hg@fc1+b1)@fc2+b2
    k_fc<<<G, D>>>(hg_in, fc1_w, fc1_b, tbuf, 1);
    k_fc<<<G, D>>>(tbuf, fc2_w, fc2_b, (float*)d_out, 0);
}

// round 3
// speedup vs baseline: 1.7770x; 1.7770x over previous
#include <cuda_runtime.h>
#include <cuda_bf16.h>

// GGIN: 3-layer GIN + graph readout. N=100000, E=1600000, D=128, G=1024, L=3, C=128.
//
// R3: CSR-ified edge aggregation (gather, not atomic scatter).
//   once:  CSR(dst -> list of src) built on device (hist + scan + fill)
//   layer: m[v] = (1+eps)h[v] + sum_{u in N(v)} h[u]      (warp-per-node gather)
//          h'   = relu(m @ W[l] + pg_l[gid])              (fp32x2 SIMT GEMM)
//          pg_l = hg@W + ctx@Wc + b  (per-graph), hg' = segsum(h') fused in epilogue

#define D 128
#define MAXN 100000
#define MAXG 1024
#define MAXE 1600000

// ---- static scratch ----
__device__ float g_h0[(size_t)MAXN * D];
__device__ float g_h1[(size_t)MAXN * D];
__device__ float g_m[(size_t)MAXN * D];
__device__ float g_hgA[MAXG * D];
__device__ float g_hgB[MAXG * D];
__device__ float g_ctx[MAXG * D];
__device__ float g_pg[MAXG * D];
__device__ float g_t[MAXG * D];
__device__ float g_lead[D];
__device__ int   g_rowptr[MAXN + 1];
__device__ int   g_cursor[MAXN];
__device__ int   g_csr[MAXE];
__device__ int   g_bsum[256];

// ---- helpers ----
__device__ __forceinline__ void red4(float* p, float4 v) {
    asm volatile("red.global.add.v4.f32 [%0], {%1,%2,%3,%4};"
                 :: "l"(p), "f"(v.x), "f"(v.y), "f"(v.z), "f"(v.w) : "memory");
}
__device__ __forceinline__ unsigned long long pack2(float x, float y) {
    unsigned long long r;
    asm("mov.b64 %0, {%1,%2};" : "=l"(r) : "f"(x), "f"(y));
    return r;
}
__device__ __forceinline__ void fma2(unsigned long long& d, unsigned long long a, unsigned long long b) {
    asm("fma.rn.f32x2 %0, %1, %2, %0;" : "+l"(d) : "l"(a), "l"(b));
}
__device__ __forceinline__ float2 unpack2(unsigned long long v) {
    float2 r;
    asm("mov.b64 {%0,%1}, %2;" : "=f"(r.x), "=f"(r.y) : "l"(v));
    return r;
}

// ---- zero (float4 / int) ----
__global__ void k_zero(float4* __restrict__ p, int n4) {
    int stride = gridDim.x * blockDim.x;
    for (int i = blockIdx.x * blockDim.x + threadIdx.x; i < n4; i += stride)
        p[i] = make_float4(0.f, 0.f, 0.f, 0.f);
}
__global__ void k_zeroi(int* __restrict__ p, int n) {
    int i = blockIdx.x * blockDim.x + threadIdx.x;
    if (i < n) p[i] = 0;
}

// ================= CSR build =================
__global__ void k_hist(const int* __restrict__ dst, int* __restrict__ deg, int nE) {
    int e = blockIdx.x * blockDim.x + threadIdx.x;
    if (e < nE) atomicAdd(deg + __ldg(dst + e), 1);
}
// pass a: per-1024-chunk sums
__global__ void k_bsum(const int* __restrict__ deg, int* __restrict__ bsum, int n) {
    __shared__ int sh[8];
    int base = blockIdx.x * 1024 + threadIdx.x * 4;
    int s = 0;
    #pragma unroll
    for (int j = 0; j < 4; j++) { int i = base + j; if (i < n) s += deg[i]; }
    #pragma unroll
    for (int o = 16; o > 0; o >>= 1) s += __shfl_down_sync(0xffffffffu, s, o);
    if ((threadIdx.x & 31) == 0) sh[threadIdx.x >> 5] = s;
    __syncthreads();
    if (threadIdx.x == 0) {
        int t = 0;
        for (int w = 0; w < 8; w++) t += sh[w];
        bsum[blockIdx.x] = t;
    }
}
// pass b: serial exclusive scan of chunk sums; also set rowptr[n]=E
__global__ void k_scansum(int* __restrict__ bsum, int nb, int* __restrict__ rowptr, int n, int nE) {
    if (threadIdx.x == 0) {
        int acc = 0;
        for (int i = 0; i < nb; i++) { int v = bsum[i]; bsum[i] = acc; acc += v; }
        rowptr[n] = nE;
    }
}
// pass c: per-chunk exclusive scan + offset; write rowptr and cursor
__global__ void k_scanfin(int* __restrict__ deg, const int* __restrict__ bsum,
                          int* __restrict__ rowptr, int* __restrict__ cursor, int n) {
    __shared__ int wsum[8];
    __shared__ int wexc[8];
    int lane = threadIdx.x & 31, warp = threadIdx.x >> 5;
    int base = blockIdx.x * 1024 + threadIdx.x * 4;
    int v[4]; int s = 0;
    #pragma unroll
    for (int j = 0; j < 4; j++) { int i = base + j; v[j] = (i < n) ? deg[i] : 0; s += v[j]; }
    int pre = s;
    #pragma unroll
    for (int o = 1; o < 32; o <<= 1) {
        int t = __shfl_up_sync(0xffffffffu, pre, o);
        if (lane >= o) pre += t;
    }
    int excl = pre - s;  // exclusive within warp
    if (lane == 31) wsum[warp] = pre;
    __syncthreads();
    if (threadIdx.x == 0) {
        int acc = 0;
        for (int w = 0; w < 8; w++) { wexc[w] = acc; acc += wsum[w]; }
    }
    __syncthreads();
    int off = bsum[blockIdx.x] + wexc[warp] + excl;
    #pragma unroll
    for (int j = 0; j < 4; j++) {
        int i = base + j;
        if (i < n) { rowptr[i] = off; cursor[i] = off; off += v[j]; }
    }
}
__global__ void k_fill(const int* __restrict__ src, const int* __restrict__ dst,
                       int* __restrict__ cursor, int* __restrict__ csr, int nE) {
    int e = blockIdx.x * blockDim.x + threadIdx.x;
    if (e < nE) {
        int pos = atomicAdd(cursor + __ldg(dst + e), 1);
        csr[pos] = __ldg(src + e);
    }
}

// ================= per-layer kernels =================
// warp-per-node gather: m[v] = sc*h[v] + sum h[u]
__global__ void k_gather(const float4* __restrict__ h4, const int* __restrict__ rowptr,
                         const int* __restrict__ csr, float4* __restrict__ m4,
                         const float* __restrict__ epsArr, int l, int n) {
    int t = blockIdx.x * blockDim.x + threadIdx.x;
    int v = t >> 5, lane = t & 31;
    if (v >= n) return;
    const float sc = 1.0f + __ldg(epsArr + l);
    int beg = __ldg(rowptr + v), end = __ldg(rowptr + v + 1);
    float4 hv = __ldg(h4 + (size_t)v * 32 + lane);
    float4 acc = make_float4(sc * hv.x, sc * hv.y, sc * hv.z, sc * hv.w);
    int i = beg;
    for (; i + 1 < end; i += 2) {
        int u0 = __ldg(csr + i), u1 = __ldg(csr + i + 1);
        float4 a = __ldg(h4 + (size_t)u0 * 32 + lane);
        float4 bv = __ldg(h4 + (size_t)u1 * 32 + lane);
        acc.x += a.x + bv.x; acc.y += a.y + bv.y;
        acc.z += a.z + bv.z; acc.w += a.w + bv.w;
    }
    if (i < end) {
        int u0 = __ldg(csr + i);
        float4 a = __ldg(h4 + (size_t)u0 * 32 + lane);
        acc.x += a.x; acc.y += a.y; acc.z += a.z; acc.w += a.w;
    }
    m4[(size_t)v * 32 + lane] = acc;
}

// lead sum
__global__ void k_lead(const float* __restrict__ lf, float* __restrict__ lead, int nl) {
    int d = threadIdx.x;
    float a = 0.f;
    for (int r = 0; r < nl; r++) a += lf[r * D + d];
    lead[d] = a;
}
__global__ void k_addlead(float* __restrict__ ctx, const float* __restrict__ lead, int n) {
    int i = blockIdx.x * blockDim.x + threadIdx.x;
    if (i < n) ctx[i] += lead[i & (D - 1)];
}
// row segment-sum scatter (init pooling only)
__global__ void k_scatter_rows(const float4* __restrict__ rows, const int* __restrict__ ids,
                               float* __restrict__ out, int n) {
    int t = blockIdx.x * blockDim.x + threadIdx.x;
    int r = t >> 5, lane = t & 31;
    if (r >= n) return;
    int g = __ldg(ids + r);
    float4 v = __ldg(rows + (size_t)r * 32 + lane);
    red4(out + (size_t)g * D + lane * 4, v);
}
// per-graph bias: pg[g] = hg[g]@W + ctx[g]@Wc + b
__global__ void k_pg(const float* __restrict__ hg, const float* __restrict__ ctx,
                     const float* __restrict__ W, const float* __restrict__ Wc,
                     const float* __restrict__ b, float* __restrict__ pg) {
    int g = blockIdx.x, d = threadIdx.x;
    __shared__ float sh[D], sc[D];
    sh[d] = hg[g * D + d];
    sc[d] = ctx[g * D + d];
    __syncthreads();
    float acc = __ldg(b + d);
    #pragma unroll 8
    for (int k = 0; k < D; k++) {
        acc += sh[k] * __ldg(W + k * D + d);
        acc += sc[k] * __ldg(Wc + k * D + d);
    }
    pg[g * D + d] = acc;
}
// small dense
__global__ void k_fc(const float* __restrict__ in, const float* __restrict__ Wm,
                     const float* __restrict__ bias, float* __restrict__ out, int do_relu) {
    int g = blockIdx.x, d = threadIdx.x;
    __shared__ float s[D];
    s[d] = in[g * D + d];
    __syncthreads();
    float acc = __ldg(bias + d);
    #pragma unroll 8
    for (int k = 0; k < D; k++) acc += s[k] * __ldg(Wm + k * D + d);
    if (do_relu) acc = fmaxf(acc, 0.f);
    out[g * D + d] = acc;
}

// node GEMM: Hout = relu(M @ W + pg[gid]); hgOut += segsum(Hout)
#define SMEM_GEMM ((128 * 132 + 128 * 128) * 4)
__global__ void __launch_bounds__(256, 1)
k_gemm(const float4* __restrict__ M4, const float4* __restrict__ Wl4,
       const float* __restrict__ pgv, const int* __restrict__ gid,
       float4* __restrict__ Hout4, float* __restrict__ hgOut, int nRows) {
    extern __shared__ float smem[];
    float* As = smem;              // [128][132]
    float* Bs = smem + 128 * 132;  // [128][128]
    const int tid = threadIdx.x;
    const int m0 = blockIdx.x * 128;

    float4* Bs4 = (float4*)Bs;
    #pragma unroll
    for (int i = 0; i < 16; i++) {
        int li = tid + i * 256;
        Bs4[li] = __ldg(Wl4 + li);
    }
    #pragma unroll
    for (int i = 0; i < 16; i++) {
        int li = tid + i * 256;
        int m = li >> 5, k4 = li & 31;
        int mg = m0 + m;
        float4 v = (mg < nRows) ? __ldg(M4 + (size_t)mg * 32 + k4)
                                : make_float4(0.f, 0.f, 0.f, 0.f);
        *(float4*)(As + m * 132 + k4 * 4) = v;
    }
    __syncthreads();

    const int tx = tid & 15, ty = tid >> 4;
    unsigned long long acc[8][4];
    #pragma unroll
    for (int i = 0; i < 8; i++)
        #pragma unroll
        for (int j = 0; j < 4; j++) acc[i][j] = 0ull;

    const float* a0 = As + (ty * 4) * 132;
    const float* a1 = As + (64 + ty * 4) * 132;

    #pragma unroll 8
    for (int k = 0; k < 128; k++) {
        float4 b0 = *(const float4*)(Bs + k * 128 + tx * 4);
        float4 b1 = *(const float4*)(Bs + k * 128 + 64 + tx * 4);
        unsigned long long bb0 = pack2(b0.x, b0.y), bb1 = pack2(b0.z, b0.w);
        unsigned long long bb2 = pack2(b1.x, b1.y), bb3 = pack2(b1.z, b1.w);
        #pragma unroll
        for (int i = 0; i < 4; i++) {
            float a = a0[i * 132 + k];
            unsigned long long aa = pack2(a, a);
            fma2(acc[i][0], aa, bb0);
            fma2(acc[i][1], aa, bb1);
            fma2(acc[i][2], aa, bb2);
            fma2(acc[i][3], aa, bb3);
        }
        #pragma unroll
        for (int i = 0; i < 4; i++) {
            float a = a1[i * 132 + k];
            unsigned long long aa = pack2(a, a);
            fma2(acc[4 + i][0], aa, bb0);
            fma2(acc[4 + i][1], aa, bb1);
            fma2(acc[4 + i][2], aa, bb2);
            fma2(acc[4 + i][3], aa, bb3);
        }
    }

    #pragma unroll
    for (int i = 0; i < 8; i++) {
        int m = (i < 4) ? (ty * 4 + i) : (64 + ty * 4 + i - 4);
        int mg = m0 + m;
        if (mg >= nRows) continue;
        int g = __ldg(gid + mg);
        const float4* pgr = (const float4*)(pgv + (size_t)g * D);
        float4 p0 = __ldg(pgr + tx);
        float4 p1 = __ldg(pgr + 16 + tx);
        float2 t0 = unpack2(acc[i][0]), t1 = unpack2(acc[i][1]);
        float2 t2 = unpack2(acc[i][2]), t3 = unpack2(acc[i][3]);
        float4 o0 = make_float4(fmaxf(t0.x + p0.x, 0.f), fmaxf(t0.y + p0.y, 0.f),
                                fmaxf(t1.x + p0.z, 0.f), fmaxf(t1.y + p0.w, 0.f));
        float4 o1 = make_float4(fmaxf(t2.x + p1.x, 0.f), fmaxf(t2.y + p1.y, 0.f),
                                fmaxf(t3.x + p1.z, 0.f), fmaxf(t3.y + p1.w, 0.f));
        Hout4[(size_t)mg * 32 + tx] = o0;
        Hout4[(size_t)mg * 32 + 16 + tx] = o1;
        red4(hgOut + (size_t)g * D + tx * 4, o0);
        red4(hgOut + (size_t)g * D + 64 + tx * 4, o1);
    }
}

extern "C" void kernel_launch(void* const* d_in, const int* in_sizes, int n_in,
                              void* d_out, int out_size) {
    const float* x        = (const float*)d_in[0];
    const int*   src      = (const int*)d_in[1];
    const int*   dst      = (const int*)d_in[2];
    const int*   gids     = (const int*)d_in[3];
    const float* initf    = (const float*)d_in[4];
    const int*   init_ids = (const int*)d_in[5];
    const float* leadf    = (const float*)d_in[6];
    const float* W        = (const float*)d_in[7];
    const float* Wc       = (const float*)d_in[8];
    const float* b        = (const float*)d_in[9];
    const float* eps      = (const float*)d_in[10];
    const float* fc1_w    = (const float*)d_in[11];
    const float* fc1_b    = (const float*)d_in[12];
    const float* fc2_w    = (const float*)d_in[13];
    const float* fc2_b    = (const float*)d_in[14];

    const int N  = in_sizes[0] / D;
    const int E  = in_sizes[1];
    const int NI = in_sizes[4] / D;
    const int NL = in_sizes[6] / D;
    const int L  = in_sizes[10];
    const int G  = out_size / D;

    float *h0, *h1, *mbuf, *hgA, *hgB, *ctx, *pg, *tbuf, *lead;
    int *rowptr, *cursor, *csr, *bsum;
    cudaGetSymbolAddress((void**)&h0, g_h0);
    cudaGetSymbolAddress((void**)&h1, g_h1);
    cudaGetSymbolAddress((void**)&mbuf, g_m);
    cudaGetSymbolAddress((void**)&hgA, g_hgA);
    cudaGetSymbolAddress((void**)&hgB, g_hgB);
    cudaGetSymbolAddress((void**)&ctx, g_ctx);
    cudaGetSymbolAddress((void**)&pg, g_pg);
    cudaGetSymbolAddress((void**)&tbuf, g_t);
    cudaGetSymbolAddress((void**)&lead, g_lead);
    cudaGetSymbolAddress((void**)&rowptr, g_rowptr);
    cudaGetSymbolAddress((void**)&cursor, g_cursor);
    cudaGetSymbolAddress((void**)&csr, g_csr);
    cudaGetSymbolAddress((void**)&bsum, g_bsum);

    cudaFuncSetAttribute(k_gemm, cudaFuncAttributeMaxDynamicSharedMemorySize, SMEM_GEMM);

    const int NB = (N + 1023) / 1024;

    // ---- CSR build (once per call) ----
    k_zeroi<<<(N + 255) / 256, 256>>>(cursor, N);                // cursor <- deg histogram
    k_hist<<<(E + 255) / 256, 256>>>(dst, cursor, E);
    k_bsum<<<NB, 256>>>(cursor, bsum, N);
    k_scansum<<<1, 32>>>(bsum, NB, rowptr, N, E);
    k_scanfin<<<NB, 256>>>(cursor, bsum, rowptr, cursor, N);     // rowptr + cursor
    k_fill<<<(E + 255) / 256, 256>>>(src, dst, cursor, csr, E);

    // ---- global context ----
    k_zero<<<32, 256>>>((float4*)hgA, G * D / 4);
    k_zero<<<32, 256>>>((float4*)ctx, G * D / 4);
    k_lead<<<1, D>>>(leadf, lead, NL);
    k_scatter_rows<<<(N * 32 + 255) / 256, 256>>>((const float4*)x, gids, hgA, N);
    k_scatter_rows<<<(NI * 32 + 255) / 256, 256>>>((const float4*)initf, init_ids, ctx, NI);
    k_addlead<<<(G * D + 255) / 256, 256>>>(ctx, lead, G * D);

    const float* hin = x;
    float* hbuf[2] = {h0, h1};
    float* hg_in = hgA;
    float* hg_out = hgB;

    for (int l = 0; l < L; l++) {
        float* hout = hbuf[l & 1];
        k_gather<<<(N * 32 + 255) / 256, 256>>>((const float4*)hin, rowptr, csr,
                                                (float4*)mbuf, eps, l, N);
        k_pg<<<G, D>>>(hg_in, ctx, W + (size_t)l * D * D, Wc + (size_t)l * D * D, b + l * D, pg);
        k_zero<<<32, 256>>>((float4*)hg_out, G * D / 4);
        k_gemm<<<(N + 127) / 128, 256, SMEM_GEMM>>>(
            (const float4*)mbuf, (const float4*)(W + (size_t)l * D * D),
            pg, gids, (float4*)hout, hg_out, N);
        hin = hout;
        float* tmp = hg_in; hg_in = hg_out; hg_out = tmp;
    }

    k_fc<<<G, D>>>(hg_in, fc1_w, fc1_b, tbuf, 1);
    k_fc<<<G, D>>>(tbuf, fc2_w, fc2_b, (float*)d_out, 0);
}